// round 6
// baseline (speedup 1.0000x reference)
#include <cuda_runtime.h>
#include <cuda_fp16.h>

#define N_NODES 50000
#define N_EDGES 800000
#define SCAN_T  1024
#define CHUNK   49           // 1024*49 = 50176 >= 50000
#define SCAN_PAD (SCAN_T * CHUNK)

#define HEAD_SMEM    ((64*132 + 64*104 + 128*26 + 128) * 4)

// -------- scratch (static device allocations; no cudaMalloc allowed) --------
__device__ __half g_h1h[N_NODES * 64];   // GEMM out (half) -> agg gather input
__device__ __half g_h2h[N_NODES * 64];   // agg1 out (half) -> gemm2 input
__device__ float  g_h2f[N_NODES * 64];   // agg2 out (fp32) -> head input
__device__ int    g_deg[N_NODES];
__device__ int    g_rowptr[N_NODES + 1];
__device__ int    g_cursor[N_NODES];
__device__ int2   g_edge[N_EDGES];       // (src, weight-bits)

// ---------------------------- PTX helpers -----------------------------------
__device__ __forceinline__ unsigned smem_u32(const void* p) {
    return (unsigned)__cvta_generic_to_shared(p);
}
__device__ __forceinline__ void ldsm_x4(unsigned& r0, unsigned& r1,
                                        unsigned& r2, unsigned& r3, unsigned a) {
    asm volatile("ldmatrix.sync.aligned.m8n8.x4.shared.b16 {%0,%1,%2,%3},[%4];\n"
                 : "=r"(r0), "=r"(r1), "=r"(r2), "=r"(r3) : "r"(a));
}
__device__ __forceinline__ void ldsm_x4_t(unsigned& r0, unsigned& r1,
                                          unsigned& r2, unsigned& r3, unsigned a) {
    asm volatile("ldmatrix.sync.aligned.m8n8.x4.trans.shared.b16 {%0,%1,%2,%3},[%4];\n"
                 : "=r"(r0), "=r"(r1), "=r"(r2), "=r"(r3) : "r"(a));
}
__device__ __forceinline__ void mma16816(float* d, unsigned a0, unsigned a1,
                                         unsigned a2, unsigned a3,
                                         unsigned b0, unsigned b1) {
    asm volatile("mma.sync.aligned.m16n8k16.row.col.f32.f16.f16.f32 "
                 "{%0,%1,%2,%3},{%4,%5,%6,%7},{%8,%9},{%0,%1,%2,%3};\n"
                 : "+f"(d[0]), "+f"(d[1]), "+f"(d[2]), "+f"(d[3])
                 : "r"(a0), "r"(a1), "r"(a2), "r"(a3), "r"(b0), "r"(b1));
}

// ---------------------------- CSR construction -----------------------------
__global__ void hist_kernel(const int4* __restrict__ dst4) {
    int i = blockIdx.x * blockDim.x + threadIdx.x;
    if (i < N_EDGES / 4) {
        int4 d = dst4[i];
        atomicAdd(&g_deg[d.x], 1);
        atomicAdd(&g_deg[d.y], 1);
        atomicAdd(&g_deg[d.z], 1);
        atomicAdd(&g_deg[d.w], 1);
    }
}

__global__ void scan_fused_kernel() {
    extern __shared__ int sdeg[];
    __shared__ int warpsum[32];
    int t = threadIdx.x;
    for (int i = t; i < SCAN_PAD; i += SCAN_T)
        sdeg[i] = (i < N_NODES) ? g_deg[i] : 0;
    __syncthreads();

    int base = t * CHUNK;
    int sum = 0;
    for (int j = 0; j < CHUNK; j++) sum += sdeg[base + j];

    int lane = t & 31, wid = t >> 5;
    int incl = sum;
#pragma unroll
    for (int o = 1; o < 32; o <<= 1) {
        int u = __shfl_up_sync(0xffffffffu, incl, o);
        if (lane >= o) incl += u;
    }
    if (lane == 31) warpsum[wid] = incl;
    __syncthreads();
    if (wid == 0) {
        int v = warpsum[lane];
        int wi = v;
#pragma unroll
        for (int o = 1; o < 32; o <<= 1) {
            int u = __shfl_up_sync(0xffffffffu, wi, o);
            if (lane >= o) wi += u;
        }
        warpsum[lane] = wi - v;
        if (lane == 31) g_rowptr[N_NODES] = wi;
    }
    __syncthreads();

    int run = warpsum[wid] + (incl - sum);
    for (int j = 0; j < CHUNK; j++) {
        int d = sdeg[base + j];
        sdeg[base + j] = run;
        run += d;
    }
    __syncthreads();
    for (int i = t; i < N_NODES; i += SCAN_T) {
        int v = sdeg[i];
        g_rowptr[i] = v;
        g_cursor[i] = v;
    }
}

__global__ void scatter_kernel(const int4* __restrict__ src4,
                               const int4* __restrict__ dst4,
                               const float4* __restrict__ w4) {
    int i = blockIdx.x * blockDim.x + threadIdx.x;
    if (i >= N_EDGES / 4) return;
    int4   s = src4[i];
    int4   d = dst4[i];
    float4 w = w4[i];
    int p0 = atomicAdd(&g_cursor[d.x], 1);
    int p1 = atomicAdd(&g_cursor[d.y], 1);
    int p2 = atomicAdd(&g_cursor[d.z], 1);
    int p3 = atomicAdd(&g_cursor[d.w], 1);
    g_edge[p0] = make_int2(s.x, __float_as_int(w.x));
    g_edge[p1] = make_int2(s.y, __float_as_int(w.y));
    g_edge[p2] = make_int2(s.z, __float_as_int(w.z));
    g_edge[p3] = make_int2(s.w, __float_as_int(w.w));
}

// ------------------- HMMA GEMM: 64 rows x 64 cols per block -----------------
// fp32-input variant (layer 1: A = x)
__global__ void gemm64_hmma_f32(const float* __restrict__ A,
                                const float* __restrict__ W,
                                __half* __restrict__ outh) {
    __shared__ __align__(16) __half As[64 * 72];
    __shared__ __align__(16) __half Ws[64 * 72];
    const int tid  = threadIdx.x;
    const int lane = tid & 31;
    const int w    = tid >> 5;
    const int row0 = blockIdx.x * 64;

    const float4* W4 = reinterpret_cast<const float4*>(W);
    for (int i = tid; i < 1024; i += 128) {
        float4 v = W4[i];
        int k = i >> 4, n = (i & 15) * 4;
        __half2* p = reinterpret_cast<__half2*>(&Ws[k * 72 + n]);
        p[0] = __floats2half2_rn(v.x, v.y);
        p[1] = __floats2half2_rn(v.z, v.w);
    }
    const float4* A4 = reinterpret_cast<const float4*>(A);
    for (int i = tid; i < 1024; i += 128) {
        int r = i >> 4, k = (i & 15) * 4;
        int grow = row0 + r;
        float4 v = (grow < N_NODES) ? A4[grow * 16 + (k >> 2)]
                                    : make_float4(0.f, 0.f, 0.f, 0.f);
        __half2* p = reinterpret_cast<__half2*>(&As[r * 72 + k]);
        p[0] = __floats2half2_rn(v.x, v.y);
        p[1] = __floats2half2_rn(v.z, v.w);
    }
    __syncthreads();

    float d[4][2][4];
#pragma unroll
    for (int m = 0; m < 4; m++)
#pragma unroll
        for (int j = 0; j < 2; j++)
#pragma unroll
            for (int c = 0; c < 4; c++) d[m][j][c] = 0.f;

    const int lrow = lane & 15;
    const int lcol = (lane >> 4) * 8;

#pragma unroll
    for (int ks = 0; ks < 4; ks++) {
        const int kk = ks * 16;
        unsigned b0, b1, b2, b3;
        ldsm_x4_t(b0, b1, b2, b3,
                  smem_u32(&Ws[(kk + lrow) * 72 + w * 16 + lcol]));
#pragma unroll
        for (int m = 0; m < 4; m++) {
            unsigned a0, a1, a2, a3;
            ldsm_x4(a0, a1, a2, a3,
                    smem_u32(&As[(m * 16 + lrow) * 72 + kk + lcol]));
            mma16816(d[m][0], a0, a1, a2, a3, b0, b1);
            mma16816(d[m][1], a0, a1, a2, a3, b2, b3);
        }
    }

    __half2* out2 = reinterpret_cast<__half2*>(outh);
    const int r_in = lane >> 2;
    const int cpair = (lane & 3);
#pragma unroll
    for (int m = 0; m < 4; m++) {
#pragma unroll
        for (int j = 0; j < 2; j++) {
            int col2 = (w * 16 + j * 8) / 2 + cpair;
            int g0 = row0 + m * 16 + r_in;
            int g1 = g0 + 8;
            if (g0 < N_NODES)
                out2[g0 * 32 + col2] = __floats2half2_rn(d[m][j][0], d[m][j][1]);
            if (g1 < N_NODES)
                out2[g1 * 32 + col2] = __floats2half2_rn(d[m][j][2], d[m][j][3]);
        }
    }
}

// half-input variant (layer 2: A = agg1 half output) — no CVT in staging
__global__ void gemm64_hmma_f16(const __half* __restrict__ A,
                                const float* __restrict__ W,
                                __half* __restrict__ outh) {
    __shared__ __align__(16) __half As[64 * 72];
    __shared__ __align__(16) __half Ws[64 * 72];
    const int tid  = threadIdx.x;
    const int lane = tid & 31;
    const int w    = tid >> 5;
    const int row0 = blockIdx.x * 64;

    const float4* W4 = reinterpret_cast<const float4*>(W);
    for (int i = tid; i < 1024; i += 128) {
        float4 v = W4[i];
        int k = i >> 4, n = (i & 15) * 4;
        __half2* p = reinterpret_cast<__half2*>(&Ws[k * 72 + n]);
        p[0] = __floats2half2_rn(v.x, v.y);
        p[1] = __floats2half2_rn(v.z, v.w);
    }
    const uint2* A2 = reinterpret_cast<const uint2*>(A);   // 4 halves each
    for (int i = tid; i < 1024; i += 128) {
        int r = i >> 4, k4 = (i & 15);
        int grow = row0 + r;
        uint2 v = (grow < N_NODES) ? A2[grow * 16 + k4] : make_uint2(0u, 0u);
        *reinterpret_cast<uint2*>(&As[r * 72 + k4 * 4]) = v;
    }
    __syncthreads();

    float d[4][2][4];
#pragma unroll
    for (int m = 0; m < 4; m++)
#pragma unroll
        for (int j = 0; j < 2; j++)
#pragma unroll
            for (int c = 0; c < 4; c++) d[m][j][c] = 0.f;

    const int lrow = lane & 15;
    const int lcol = (lane >> 4) * 8;

#pragma unroll
    for (int ks = 0; ks < 4; ks++) {
        const int kk = ks * 16;
        unsigned b0, b1, b2, b3;
        ldsm_x4_t(b0, b1, b2, b3,
                  smem_u32(&Ws[(kk + lrow) * 72 + w * 16 + lcol]));
#pragma unroll
        for (int m = 0; m < 4; m++) {
            unsigned a0, a1, a2, a3;
            ldsm_x4(a0, a1, a2, a3,
                    smem_u32(&As[(m * 16 + lrow) * 72 + kk + lcol]));
            mma16816(d[m][0], a0, a1, a2, a3, b0, b1);
            mma16816(d[m][1], a0, a1, a2, a3, b2, b3);
        }
    }

    __half2* out2 = reinterpret_cast<__half2*>(outh);
    const int r_in = lane >> 2;
    const int cpair = (lane & 3);
#pragma unroll
    for (int m = 0; m < 4; m++) {
#pragma unroll
        for (int j = 0; j < 2; j++) {
            int col2 = (w * 16 + j * 8) / 2 + cpair;
            int g0 = row0 + m * 16 + r_in;
            int g1 = g0 + 8;
            if (g0 < N_NODES)
                out2[g0 * 32 + col2] = __floats2half2_rn(d[m][j][0], d[m][j][1]);
            if (g1 < N_NODES)
                out2[g1 * 32 + col2] = __floats2half2_rn(d[m][j][2], d[m][j][3]);
        }
    }
}

// -------------------- CSR aggregation + bias + swish ------------------------
// HALF_OUT: write half2 (same rn rounding gemm2 would apply — bit-identical)
template<bool HALF_OUT>
__global__ void agg_swish_kernel(const __half2* __restrict__ hp,
                                 const float* __restrict__ bias,
                                 void* __restrict__ outv) {
    int warp = (blockIdx.x * blockDim.x + threadIdx.x) >> 5;
    int lane = threadIdx.x & 31;
    if (warp >= N_NODES) return;
    int beg = g_rowptr[warp];
    int end = g_rowptr[warp + 1];
    float2 acc = make_float2(0.f, 0.f);
    int e = beg;
    for (; e + 8 <= end; e += 8) {
        int2 ed[8];
#pragma unroll
        for (int j = 0; j < 8; j++) ed[j] = g_edge[e + j];
        float2 v[8];
#pragma unroll
        for (int j = 0; j < 8; j++) v[j] = __half22float2(hp[ed[j].x * 32 + lane]);
#pragma unroll
        for (int j = 0; j < 8; j++) {
            float w = __int_as_float(ed[j].y);
            acc.x = fmaf(w, v[j].x, acc.x);
            acc.y = fmaf(w, v[j].y, acc.y);
        }
    }
    for (; e + 2 <= end; e += 2) {
        int2 e0 = g_edge[e], e1 = g_edge[e + 1];
        float2 v0 = __half22float2(hp[e0.x * 32 + lane]);
        float2 v1 = __half22float2(hp[e1.x * 32 + lane]);
        float w0 = __int_as_float(e0.y), w1 = __int_as_float(e1.y);
        acc.x = fmaf(w0, v0.x, acc.x); acc.y = fmaf(w0, v0.y, acc.y);
        acc.x = fmaf(w1, v1.x, acc.x); acc.y = fmaf(w1, v1.y, acc.y);
    }
    if (e < end) {
        int2 e0 = g_edge[e];
        float2 v0 = __half22float2(hp[e0.x * 32 + lane]);
        float w0 = __int_as_float(e0.y);
        acc.x = fmaf(w0, v0.x, acc.x); acc.y = fmaf(w0, v0.y, acc.y);
    }
    float2 b = reinterpret_cast<const float2*>(bias)[lane];
    float ax = acc.x + b.x;
    float ay = acc.y + b.y;
    ax = ax / (1.f + __expf(-ax));
    ay = ay / (1.f + __expf(-ay));
    if (HALF_OUT) {
        reinterpret_cast<__half2*>(outv)[warp * 32 + lane] = __floats2half2_rn(ax, ay);
    } else {
        reinterpret_cast<float2*>(outv)[warp * 32 + lane] = make_float2(ax, ay);
    }
}

// --------------- fused dense(100, swish) + dense(1, sigmoid) ----------------
__global__ void gemm100_head_kernel(const float* __restrict__ A,
                                    const float* __restrict__ Wd,
                                    const float* __restrict__ bd,
                                    const float* __restrict__ Wo,
                                    const float* __restrict__ bo,
                                    float* __restrict__ out) {
    extern __shared__ float sm[];
    float* Ast  = sm;                       // [64][132]
    float* Ws   = Ast + 64 * 132;           // [64][104]
    float* part = Ws + 64 * 104;            // [128][26]
    float* woS  = part + 128 * 26;          // [100]
    const int tx = threadIdx.x;             // 0..24
    const int ty = threadIdx.y;             // 0..15
    const int tid = ty * 25 + tx;           // 0..399
    const int row0 = blockIdx.x * 128;

    for (int i = tid * 4; i < 6400; i += 1600) {
        int k = i / 100, c = i % 100;
        float4 v = *reinterpret_cast<const float4*>(Wd + i);
        *reinterpret_cast<float4*>(&Ws[k * 104 + c]) = v;
    }
    for (int i = tid * 4; i < 8192; i += 1600) {
        int r = i >> 6, k = i & 63;
        int grow = row0 + r;
        float4 v = (grow < N_NODES)
                 ? *reinterpret_cast<const float4*>(A + grow * 64 + k)
                 : make_float4(0.f, 0.f, 0.f, 0.f);
        Ast[(k + 0) * 132 + r] = v.x;
        Ast[(k + 1) * 132 + r] = v.y;
        Ast[(k + 2) * 132 + r] = v.z;
        Ast[(k + 3) * 132 + r] = v.w;
    }
    if (tid < 100) woS[tid] = Wo[tid];
    __syncthreads();

    float acc[8][4];
#pragma unroll
    for (int r = 0; r < 8; r++)
#pragma unroll
        for (int c = 0; c < 4; c++) acc[r][c] = 0.f;

#pragma unroll 2
    for (int k = 0; k < 64; k++) {
        float4 wv = *reinterpret_cast<const float4*>(&Ws[k * 104 + tx * 4]);
        float4 a0 = *reinterpret_cast<const float4*>(&Ast[k * 132 + ty * 8]);
        float4 a1 = *reinterpret_cast<const float4*>(&Ast[k * 132 + ty * 8 + 4]);
        float av[8] = {a0.x, a0.y, a0.z, a0.w, a1.x, a1.y, a1.z, a1.w};
#pragma unroll
        for (int r = 0; r < 8; r++) {
            acc[r][0] = fmaf(av[r], wv.x, acc[r][0]);
            acc[r][1] = fmaf(av[r], wv.y, acc[r][1]);
            acc[r][2] = fmaf(av[r], wv.z, acc[r][2]);
            acc[r][3] = fmaf(av[r], wv.w, acc[r][3]);
        }
    }

    float4 bv  = *reinterpret_cast<const float4*>(bd + tx * 4);
    float4 wo4 = *reinterpret_cast<const float4*>(&woS[tx * 4]);
#pragma unroll
    for (int r = 0; r < 8; r++) {
        float v0 = acc[r][0] + bv.x;
        float v1 = acc[r][1] + bv.y;
        float v2 = acc[r][2] + bv.z;
        float v3 = acc[r][3] + bv.w;
        v0 = v0 / (1.f + __expf(-v0));
        v1 = v1 / (1.f + __expf(-v1));
        v2 = v2 / (1.f + __expf(-v2));
        v3 = v3 / (1.f + __expf(-v3));
        part[(ty * 8 + r) * 26 + tx] = v0 * wo4.x + v1 * wo4.y + v2 * wo4.z + v3 * wo4.w;
    }
    __syncthreads();

    if (tid < 128) {
        int grow = row0 + tid;
        if (grow < N_NODES) {
            float s = 0.f;
#pragma unroll
            for (int j = 0; j < 25; j++) s += part[tid * 26 + j];
            out[grow] = 1.f / (1.f + __expf(-(s + bo[0])));
        }
    }
}

// -------------------------------- launcher ----------------------------------
extern "C" void kernel_launch(void* const* d_in, const int* in_sizes, int n_in,
                              void* d_out, int out_size) {
    const float* x    = (const float*)d_in[0];
    const int*   esrc = (const int*)  d_in[1];
    const int*   edst = (const int*)  d_in[2];
    const float* ew   = (const float*)d_in[3];
    const float* W1   = (const float*)d_in[4];
    const float* b1   = (const float*)d_in[5];
    const float* W2   = (const float*)d_in[6];
    const float* b2   = (const float*)d_in[7];
    const float* Wd   = (const float*)d_in[8];
    const float* bd   = (const float*)d_in[9];
    const float* Wo   = (const float*)d_in[10];
    const float* bo   = (const float*)d_in[11];
    float* out = (float*)d_out;

    __half* h1h;  __half* h2h;  float* h2f;  int* degp;
    cudaGetSymbolAddress((void**)&h1h,  g_h1h);
    cudaGetSymbolAddress((void**)&h2h,  g_h2h);
    cudaGetSymbolAddress((void**)&h2f,  g_h2f);
    cudaGetSymbolAddress((void**)&degp, g_deg);

    static cudaStream_t s2 = nullptr;
    static cudaEvent_t evFork = nullptr, evJoin = nullptr;
    if (!s2) {
        cudaStreamCreateWithFlags(&s2, cudaStreamNonBlocking);
        cudaEventCreateWithFlags(&evFork, cudaEventDisableTiming);
        cudaEventCreateWithFlags(&evJoin, cudaEventDisableTiming);
        cudaFuncSetAttribute(scan_fused_kernel,
                             cudaFuncAttributeMaxDynamicSharedMemorySize,
                             SCAN_PAD * (int)sizeof(int));
        cudaFuncSetAttribute(gemm100_head_kernel,
                             cudaFuncAttributeMaxDynamicSharedMemorySize, HEAD_SMEM);
    }

    const int aggBlocks   = (N_NODES * 32 + 255) / 256;
    const int gemmBlocks  = (N_NODES + 63) / 64;
    const int headBlocks  = (N_NODES + 127) / 128;

    // --- fork: gemm1 runs concurrent with the CSR build ---
    cudaEventRecord(evFork, 0);
    cudaStreamWaitEvent(s2, evFork, 0);
    gemm64_hmma_f32<<<gemmBlocks, 128, 0, s2>>>(x, W1, h1h);
    cudaEventRecord(evJoin, s2);

    // --- CSR build (main stream) ---
    cudaMemsetAsync(degp, 0, N_NODES * sizeof(int));
    hist_kernel<<<(N_EDGES / 4 + 255) / 256, 256>>>((const int4*)edst);
    scan_fused_kernel<<<1, SCAN_T, SCAN_PAD * sizeof(int)>>>();
    scatter_kernel<<<(N_EDGES / 4 + 255) / 256, 256>>>((const int4*)esrc,
                                                       (const int4*)edst,
                                                       (const float4*)ew);

    // --- join, then layer 1 aggregation ---
    cudaStreamWaitEvent(0, evJoin, 0);
    agg_swish_kernel<true><<<aggBlocks, 256>>>((const __half2*)h1h, b1, h2h);

    // --- layer 2 ---
    gemm64_hmma_f16<<<gemmBlocks, 128>>>(h2h, W2, h1h);
    agg_swish_kernel<false><<<aggBlocks, 256>>>((const __half2*)h1h, b2, h2f);

    // --- dense head (fused) ---
    gemm100_head_kernel<<<headBlocks, dim3(25, 16), HEAD_SMEM>>>(h2f, Wd, bd, Wo, bo, out);
}

// round 7
// speedup vs baseline: 1.0471x; 1.0471x over previous
#include <cuda_runtime.h>
#include <cuda_fp16.h>

#define N_NODES 50000
#define N_EDGES 800000
#define SCAN_T  1024
#define CHUNK   49           // 1024*49 = 50176 >= 50000
#define SCAN_PAD (SCAN_T * CHUNK)

// -------- scratch (static device allocations; no cudaMalloc allowed) --------
__device__ __half g_h1h[N_NODES * 64];   // GEMM out (half) -> agg gather input
__device__ __half g_h2h[N_NODES * 64];   // agg1 out (half) -> gemm2 input
__device__ float  g_h2f[N_NODES * 64];   // agg2 out (fp32) -> head input
__device__ int    g_deg[N_NODES];
__device__ int    g_rowptr[N_NODES + 1];
__device__ int    g_cursor[N_NODES];
__device__ int2   g_edge[N_EDGES];       // (src, weight-bits)

// ---------------------------- PTX helpers -----------------------------------
__device__ __forceinline__ unsigned smem_u32(const void* p) {
    return (unsigned)__cvta_generic_to_shared(p);
}
__device__ __forceinline__ void ldsm_x4(unsigned& r0, unsigned& r1,
                                        unsigned& r2, unsigned& r3, unsigned a) {
    asm volatile("ldmatrix.sync.aligned.m8n8.x4.shared.b16 {%0,%1,%2,%3},[%4];\n"
                 : "=r"(r0), "=r"(r1), "=r"(r2), "=r"(r3) : "r"(a));
}
__device__ __forceinline__ void ldsm_x4_t(unsigned& r0, unsigned& r1,
                                          unsigned& r2, unsigned& r3, unsigned a) {
    asm volatile("ldmatrix.sync.aligned.m8n8.x4.trans.shared.b16 {%0,%1,%2,%3},[%4];\n"
                 : "=r"(r0), "=r"(r1), "=r"(r2), "=r"(r3) : "r"(a));
}
__device__ __forceinline__ void mma16816(float* d, unsigned a0, unsigned a1,
                                         unsigned a2, unsigned a3,
                                         unsigned b0, unsigned b1) {
    asm volatile("mma.sync.aligned.m16n8k16.row.col.f32.f16.f16.f32 "
                 "{%0,%1,%2,%3},{%4,%5,%6,%7},{%8,%9},{%0,%1,%2,%3};\n"
                 : "+f"(d[0]), "+f"(d[1]), "+f"(d[2]), "+f"(d[3])
                 : "r"(a0), "r"(a1), "r"(a2), "r"(a3), "r"(b0), "r"(b1));
}

// ---------------------------- CSR construction -----------------------------
__global__ void hist_kernel(const int* __restrict__ dst) {
    int base = (blockIdx.x * blockDim.x + threadIdx.x) * 8;
#pragma unroll
    for (int j = 0; j < 8; j++) {
        int i = base + j;
        if (i < N_EDGES) atomicAdd(&g_deg[dst[i]], 1);
    }
}

__global__ void scan_fused_kernel() {
    extern __shared__ int sdeg[];
    __shared__ int warpsum[32];
    int t = threadIdx.x;
    for (int i = t; i < SCAN_PAD; i += SCAN_T)
        sdeg[i] = (i < N_NODES) ? g_deg[i] : 0;
    __syncthreads();

    int base = t * CHUNK;
    int sum = 0;
    for (int j = 0; j < CHUNK; j++) sum += sdeg[base + j];

    int lane = t & 31, wid = t >> 5;
    int incl = sum;
#pragma unroll
    for (int o = 1; o < 32; o <<= 1) {
        int u = __shfl_up_sync(0xffffffffu, incl, o);
        if (lane >= o) incl += u;
    }
    if (lane == 31) warpsum[wid] = incl;
    __syncthreads();
    if (wid == 0) {
        int v = warpsum[lane];
        int wi = v;
#pragma unroll
        for (int o = 1; o < 32; o <<= 1) {
            int u = __shfl_up_sync(0xffffffffu, wi, o);
            if (lane >= o) wi += u;
        }
        warpsum[lane] = wi - v;
        if (lane == 31) g_rowptr[N_NODES] = wi;
    }
    __syncthreads();

    int run = warpsum[wid] + (incl - sum);
    for (int j = 0; j < CHUNK; j++) {
        int d = sdeg[base + j];
        sdeg[base + j] = run;
        run += d;
    }
    __syncthreads();
    for (int i = t; i < N_NODES; i += SCAN_T) {
        int v = sdeg[i];
        g_rowptr[i] = v;
        g_cursor[i] = v;
    }
}

__global__ void scatter_kernel(const int* __restrict__ src,
                               const int* __restrict__ dst,
                               const float* __restrict__ w) {
    int base = (blockIdx.x * blockDim.x + threadIdx.x) * 8;
#pragma unroll
    for (int j = 0; j < 8; j++) {
        int i = base + j;
        if (i < N_EDGES) {
            int pos = atomicAdd(&g_cursor[dst[i]], 1);
            g_edge[pos] = make_int2(src[i], __float_as_int(w[i]));
        }
    }
}

// ------------------- HMMA GEMM: 64 rows x 64 cols per block -----------------
// fp32-input variant (layer 1: A = x)
__global__ void gemm64_hmma_f32(const float* __restrict__ A,
                                const float* __restrict__ W,
                                __half* __restrict__ outh) {
    __shared__ __align__(16) __half As[64 * 72];
    __shared__ __align__(16) __half Ws[64 * 72];
    const int tid  = threadIdx.x;
    const int lane = tid & 31;
    const int w    = tid >> 5;
    const int row0 = blockIdx.x * 64;

    const float4* W4 = reinterpret_cast<const float4*>(W);
    for (int i = tid; i < 1024; i += 128) {
        float4 v = W4[i];
        int k = i >> 4, n = (i & 15) * 4;
        __half2* p = reinterpret_cast<__half2*>(&Ws[k * 72 + n]);
        p[0] = __floats2half2_rn(v.x, v.y);
        p[1] = __floats2half2_rn(v.z, v.w);
    }
    const float4* A4 = reinterpret_cast<const float4*>(A);
    for (int i = tid; i < 1024; i += 128) {
        int r = i >> 4, k = (i & 15) * 4;
        int grow = row0 + r;
        float4 v = (grow < N_NODES) ? A4[grow * 16 + (k >> 2)]
                                    : make_float4(0.f, 0.f, 0.f, 0.f);
        __half2* p = reinterpret_cast<__half2*>(&As[r * 72 + k]);
        p[0] = __floats2half2_rn(v.x, v.y);
        p[1] = __floats2half2_rn(v.z, v.w);
    }
    __syncthreads();

    float d[4][2][4];
#pragma unroll
    for (int m = 0; m < 4; m++)
#pragma unroll
        for (int j = 0; j < 2; j++)
#pragma unroll
            for (int c = 0; c < 4; c++) d[m][j][c] = 0.f;

    const int lrow = lane & 15;
    const int lcol = (lane >> 4) * 8;

#pragma unroll
    for (int ks = 0; ks < 4; ks++) {
        const int kk = ks * 16;
        unsigned b0, b1, b2, b3;
        ldsm_x4_t(b0, b1, b2, b3,
                  smem_u32(&Ws[(kk + lrow) * 72 + w * 16 + lcol]));
#pragma unroll
        for (int m = 0; m < 4; m++) {
            unsigned a0, a1, a2, a3;
            ldsm_x4(a0, a1, a2, a3,
                    smem_u32(&As[(m * 16 + lrow) * 72 + kk + lcol]));
            mma16816(d[m][0], a0, a1, a2, a3, b0, b1);
            mma16816(d[m][1], a0, a1, a2, a3, b2, b3);
        }
    }

    __half2* out2 = reinterpret_cast<__half2*>(outh);
    const int r_in = lane >> 2;
    const int cpair = (lane & 3);
#pragma unroll
    for (int m = 0; m < 4; m++) {
#pragma unroll
        for (int j = 0; j < 2; j++) {
            int col2 = (w * 16 + j * 8) / 2 + cpair;
            int g0 = row0 + m * 16 + r_in;
            int g1 = g0 + 8;
            if (g0 < N_NODES)
                out2[g0 * 32 + col2] = __floats2half2_rn(d[m][j][0], d[m][j][1]);
            if (g1 < N_NODES)
                out2[g1 * 32 + col2] = __floats2half2_rn(d[m][j][2], d[m][j][3]);
        }
    }
}

// half-input variant (layer 2: A = agg1 half output)
__global__ void gemm64_hmma_f16(const __half* __restrict__ A,
                                const float* __restrict__ W,
                                __half* __restrict__ outh) {
    __shared__ __align__(16) __half As[64 * 72];
    __shared__ __align__(16) __half Ws[64 * 72];
    const int tid  = threadIdx.x;
    const int lane = tid & 31;
    const int w    = tid >> 5;
    const int row0 = blockIdx.x * 64;

    const float4* W4 = reinterpret_cast<const float4*>(W);
    for (int i = tid; i < 1024; i += 128) {
        float4 v = W4[i];
        int k = i >> 4, n = (i & 15) * 4;
        __half2* p = reinterpret_cast<__half2*>(&Ws[k * 72 + n]);
        p[0] = __floats2half2_rn(v.x, v.y);
        p[1] = __floats2half2_rn(v.z, v.w);
    }
    const uint2* A2 = reinterpret_cast<const uint2*>(A);
    for (int i = tid; i < 1024; i += 128) {
        int r = i >> 4, k4 = (i & 15);
        int grow = row0 + r;
        uint2 v = (grow < N_NODES) ? A2[grow * 16 + k4] : make_uint2(0u, 0u);
        *reinterpret_cast<uint2*>(&As[r * 72 + k4 * 4]) = v;
    }
    __syncthreads();

    float d[4][2][4];
#pragma unroll
    for (int m = 0; m < 4; m++)
#pragma unroll
        for (int j = 0; j < 2; j++)
#pragma unroll
            for (int c = 0; c < 4; c++) d[m][j][c] = 0.f;

    const int lrow = lane & 15;
    const int lcol = (lane >> 4) * 8;

#pragma unroll
    for (int ks = 0; ks < 4; ks++) {
        const int kk = ks * 16;
        unsigned b0, b1, b2, b3;
        ldsm_x4_t(b0, b1, b2, b3,
                  smem_u32(&Ws[(kk + lrow) * 72 + w * 16 + lcol]));
#pragma unroll
        for (int m = 0; m < 4; m++) {
            unsigned a0, a1, a2, a3;
            ldsm_x4(a0, a1, a2, a3,
                    smem_u32(&As[(m * 16 + lrow) * 72 + kk + lcol]));
            mma16816(d[m][0], a0, a1, a2, a3, b0, b1);
            mma16816(d[m][1], a0, a1, a2, a3, b2, b3);
        }
    }

    __half2* out2 = reinterpret_cast<__half2*>(outh);
    const int r_in = lane >> 2;
    const int cpair = (lane & 3);
#pragma unroll
    for (int m = 0; m < 4; m++) {
#pragma unroll
        for (int j = 0; j < 2; j++) {
            int col2 = (w * 16 + j * 8) / 2 + cpair;
            int g0 = row0 + m * 16 + r_in;
            int g1 = g0 + 8;
            if (g0 < N_NODES)
                out2[g0 * 32 + col2] = __floats2half2_rn(d[m][j][0], d[m][j][1]);
            if (g1 < N_NODES)
                out2[g1 * 32 + col2] = __floats2half2_rn(d[m][j][2], d[m][j][3]);
        }
    }
}

// -------------------- CSR aggregation + bias + swish ------------------------
template<bool HALF_OUT>
__global__ void agg_swish_kernel(const __half2* __restrict__ hp,
                                 const float* __restrict__ bias,
                                 void* __restrict__ outv) {
    int warp = (blockIdx.x * blockDim.x + threadIdx.x) >> 5;
    int lane = threadIdx.x & 31;
    if (warp >= N_NODES) return;
    int beg = g_rowptr[warp];
    int end = g_rowptr[warp + 1];
    float2 acc = make_float2(0.f, 0.f);
    int e = beg;
    for (; e + 8 <= end; e += 8) {
        int2 ed[8];
#pragma unroll
        for (int j = 0; j < 8; j++) ed[j] = g_edge[e + j];
        float2 v[8];
#pragma unroll
        for (int j = 0; j < 8; j++) v[j] = __half22float2(hp[ed[j].x * 32 + lane]);
#pragma unroll
        for (int j = 0; j < 8; j++) {
            float w = __int_as_float(ed[j].y);
            acc.x = fmaf(w, v[j].x, acc.x);
            acc.y = fmaf(w, v[j].y, acc.y);
        }
    }
    for (; e + 2 <= end; e += 2) {
        int2 e0 = g_edge[e], e1 = g_edge[e + 1];
        float2 v0 = __half22float2(hp[e0.x * 32 + lane]);
        float2 v1 = __half22float2(hp[e1.x * 32 + lane]);
        float w0 = __int_as_float(e0.y), w1 = __int_as_float(e1.y);
        acc.x = fmaf(w0, v0.x, acc.x); acc.y = fmaf(w0, v0.y, acc.y);
        acc.x = fmaf(w1, v1.x, acc.x); acc.y = fmaf(w1, v1.y, acc.y);
    }
    if (e < end) {
        int2 e0 = g_edge[e];
        float2 v0 = __half22float2(hp[e0.x * 32 + lane]);
        float w0 = __int_as_float(e0.y);
        acc.x = fmaf(w0, v0.x, acc.x); acc.y = fmaf(w0, v0.y, acc.y);
    }
    float2 b = reinterpret_cast<const float2*>(bias)[lane];
    float ax = acc.x + b.x;
    float ay = acc.y + b.y;
    ax = ax / (1.f + __expf(-ax));
    ay = ay / (1.f + __expf(-ay));
    if (HALF_OUT) {
        reinterpret_cast<__half2*>(outv)[warp * 32 + lane] = __floats2half2_rn(ax, ay);
    } else {
        reinterpret_cast<float2*>(outv)[warp * 32 + lane] = make_float2(ax, ay);
    }
}

// -------- HMMA fused head: dense(100, swish) + dense(1, sigmoid) ------------
// 64 rows/block, n padded 100->112; 4 warps, warp w owns rows [16w,16w+16).
__global__ void head_hmma_kernel(const float* __restrict__ A,
                                 const float* __restrict__ Wd,
                                 const float* __restrict__ bd,
                                 const float* __restrict__ Wo,
                                 const float* __restrict__ bo,
                                 float* __restrict__ out) {
    __shared__ __align__(16) __half As[64 * 72];
    __shared__ __align__(16) __half Ws[64 * 120];   // [k][n], n padded to 112
    __shared__ float bdS[112];
    __shared__ float woS[112];
    const int tid  = threadIdx.x;
    const int lane = tid & 31;
    const int w    = tid >> 5;
    const int row0 = blockIdx.x * 64;

    // stage Wd [64][100] -> fp16 [k][n] padded with zeros
    for (int i = tid; i < 64 * 112; i += 128) {
        int k = i / 112, n = i % 112;
        float v = (n < 100) ? Wd[k * 100 + n] : 0.f;
        Ws[k * 120 + n] = __float2half_rn(v);
    }
    // stage A rows fp32->fp16
    const float4* A4 = reinterpret_cast<const float4*>(A);
    for (int i = tid; i < 1024; i += 128) {
        int r = i >> 4, k = (i & 15) * 4;
        int grow = row0 + r;
        float4 v = (grow < N_NODES) ? A4[grow * 16 + (k >> 2)]
                                    : make_float4(0.f, 0.f, 0.f, 0.f);
        __half2* p = reinterpret_cast<__half2*>(&As[r * 72 + k]);
        p[0] = __floats2half2_rn(v.x, v.y);
        p[1] = __floats2half2_rn(v.z, v.w);
    }
    if (tid < 112) {
        bdS[tid] = (tid < 100) ? bd[tid] : 0.f;
        woS[tid] = (tid < 100) ? Wo[tid] : 0.f;
    }
    __syncthreads();

    float acc[14][4];
#pragma unroll
    for (int t = 0; t < 14; t++)
#pragma unroll
        for (int c = 0; c < 4; c++) acc[t][c] = 0.f;

    const int lrow = lane & 15;
    const int lcol = (lane >> 4) * 8;

#pragma unroll
    for (int ks = 0; ks < 4; ks++) {
        const int kk = ks * 16;
        unsigned a0, a1, a2, a3;
        ldsm_x4(a0, a1, a2, a3,
                smem_u32(&As[(w * 16 + lrow) * 72 + kk + lcol]));
#pragma unroll
        for (int t2 = 0; t2 < 7; t2++) {
            unsigned b0, b1, b2, b3;
            ldsm_x4_t(b0, b1, b2, b3,
                      smem_u32(&Ws[(kk + lrow) * 120 + t2 * 16 + lcol]));
            mma16816(acc[t2 * 2],     a0, a1, a2, a3, b0, b1);
            mma16816(acc[t2 * 2 + 1], a0, a1, a2, a3, b2, b3);
        }
    }

    // epilogue: bias + swish + dot with Wo, quad reduce, sigmoid
    const int r_in = lane >> 2;
    const int c2   = (lane & 3) * 2;
    float s0 = 0.f, s1 = 0.f;
#pragma unroll
    for (int t = 0; t < 14; t++) {
        int c = t * 8 + c2;
        float bb0 = bdS[c], bb1 = bdS[c + 1];
        float ww0 = woS[c], ww1 = woS[c + 1];
        float v;
        v = acc[t][0] + bb0; v = v / (1.f + __expf(-v)); s0 = fmaf(v, ww0, s0);
        v = acc[t][1] + bb1; v = v / (1.f + __expf(-v)); s0 = fmaf(v, ww1, s0);
        v = acc[t][2] + bb0; v = v / (1.f + __expf(-v)); s1 = fmaf(v, ww0, s1);
        v = acc[t][3] + bb1; v = v / (1.f + __expf(-v)); s1 = fmaf(v, ww1, s1);
    }
    s0 += __shfl_xor_sync(0xffffffffu, s0, 1);
    s0 += __shfl_xor_sync(0xffffffffu, s0, 2);
    s1 += __shfl_xor_sync(0xffffffffu, s1, 1);
    s1 += __shfl_xor_sync(0xffffffffu, s1, 2);
    if ((lane & 3) == 0) {
        float bias0 = bo[0];
        int g0 = row0 + w * 16 + r_in;
        int g1 = g0 + 8;
        if (g0 < N_NODES) out[g0] = 1.f / (1.f + __expf(-(s0 + bias0)));
        if (g1 < N_NODES) out[g1] = 1.f / (1.f + __expf(-(s1 + bias0)));
    }
}

// -------------------------------- launcher ----------------------------------
extern "C" void kernel_launch(void* const* d_in, const int* in_sizes, int n_in,
                              void* d_out, int out_size) {
    const float* x    = (const float*)d_in[0];
    const int*   esrc = (const int*)  d_in[1];
    const int*   edst = (const int*)  d_in[2];
    const float* ew   = (const float*)d_in[3];
    const float* W1   = (const float*)d_in[4];
    const float* b1   = (const float*)d_in[5];
    const float* W2   = (const float*)d_in[6];
    const float* b2   = (const float*)d_in[7];
    const float* Wd   = (const float*)d_in[8];
    const float* bd   = (const float*)d_in[9];
    const float* Wo   = (const float*)d_in[10];
    const float* bo   = (const float*)d_in[11];
    float* out = (float*)d_out;

    __half* h1h;  __half* h2h;  float* h2f;  int* degp;
    cudaGetSymbolAddress((void**)&h1h,  g_h1h);
    cudaGetSymbolAddress((void**)&h2h,  g_h2h);
    cudaGetSymbolAddress((void**)&h2f,  g_h2f);
    cudaGetSymbolAddress((void**)&degp, g_deg);

    static cudaStream_t s2 = nullptr;
    static cudaEvent_t evFork = nullptr, evJoin = nullptr;
    if (!s2) {
        cudaStreamCreateWithFlags(&s2, cudaStreamNonBlocking);
        cudaEventCreateWithFlags(&evFork, cudaEventDisableTiming);
        cudaEventCreateWithFlags(&evJoin, cudaEventDisableTiming);
        cudaFuncSetAttribute(scan_fused_kernel,
                             cudaFuncAttributeMaxDynamicSharedMemorySize,
                             SCAN_PAD * (int)sizeof(int));
    }

    const int aggBlocks   = (N_NODES * 32 + 255) / 256;
    const int gemmBlocks  = (N_NODES + 63) / 64;
    const int edge8Blocks = (N_EDGES / 8 + 255) / 256;

    // --- fork: gemm1 runs concurrent with the CSR build ---
    cudaEventRecord(evFork, 0);
    cudaStreamWaitEvent(s2, evFork, 0);
    gemm64_hmma_f32<<<gemmBlocks, 128, 0, s2>>>(x, W1, h1h);
    cudaEventRecord(evJoin, s2);

    // --- CSR build (main stream) ---
    cudaMemsetAsync(degp, 0, N_NODES * sizeof(int));
    hist_kernel<<<edge8Blocks, 256>>>(edst);
    scan_fused_kernel<<<1, SCAN_T, SCAN_PAD * sizeof(int)>>>();
    scatter_kernel<<<edge8Blocks, 256>>>(esrc, edst, ew);

    // --- join, then layer 1 aggregation ---
    cudaStreamWaitEvent(0, evJoin, 0);
    agg_swish_kernel<true><<<aggBlocks, 256>>>((const __half2*)h1h, b1, h2h);

    // --- layer 2 ---
    gemm64_hmma_f16<<<gemmBlocks, 128>>>(h2h, W2, h1h);
    agg_swish_kernel<false><<<aggBlocks, 256>>>((const __half2*)h1h, b2, h2f);

    // --- HMMA fused head ---
    head_hmma_kernel<<<gemmBlocks, 128>>>(h2f, Wd, bd, Wo, bo, out);
}

// round 8
// speedup vs baseline: 1.0864x; 1.0375x over previous
#include <cuda_runtime.h>
#include <cuda_fp16.h>

#define N_NODES 50000
#define N_EDGES 800000
#define SCAN_T  1024
#define CHUNK   49           // 1024*49 = 50176 >= 50000
#define SCAN_PAD (SCAN_T * CHUNK)

// -------- scratch (static device allocations; no cudaMalloc allowed) --------
__device__ __half g_h1h[N_NODES * 64];   // GEMM out (half) -> agg gather input
__device__ __half g_h2h[N_NODES * 64];   // agg1 out (half) -> gemm2 input
__device__ float  g_h2f[N_NODES * 64];   // agg2 out (fp32) -> head input
__device__ int    g_deg[N_NODES];
__device__ int    g_rowptr[N_NODES + 1];
__device__ int    g_rank[N_EDGES];       // edge rank within its dst bucket
__device__ int2   g_edge[N_EDGES];       // (src, weight-bits)

// ---------------------------- PTX helpers -----------------------------------
__device__ __forceinline__ unsigned smem_u32(const void* p) {
    return (unsigned)__cvta_generic_to_shared(p);
}
__device__ __forceinline__ void ldsm_x4(unsigned& r0, unsigned& r1,
                                        unsigned& r2, unsigned& r3, unsigned a) {
    asm volatile("ldmatrix.sync.aligned.m8n8.x4.shared.b16 {%0,%1,%2,%3},[%4];\n"
                 : "=r"(r0), "=r"(r1), "=r"(r2), "=r"(r3) : "r"(a));
}
__device__ __forceinline__ void ldsm_x4_t(unsigned& r0, unsigned& r1,
                                          unsigned& r2, unsigned& r3, unsigned a) {
    asm volatile("ldmatrix.sync.aligned.m8n8.x4.trans.shared.b16 {%0,%1,%2,%3},[%4];\n"
                 : "=r"(r0), "=r"(r1), "=r"(r2), "=r"(r3) : "r"(a));
}
__device__ __forceinline__ void mma16816(float* d, unsigned a0, unsigned a1,
                                         unsigned a2, unsigned a3,
                                         unsigned b0, unsigned b1) {
    asm volatile("mma.sync.aligned.m16n8k16.row.col.f32.f16.f16.f32 "
                 "{%0,%1,%2,%3},{%4,%5,%6,%7},{%8,%9},{%0,%1,%2,%3};\n"
                 : "+f"(d[0]), "+f"(d[1]), "+f"(d[2]), "+f"(d[3])
                 : "r"(a0), "r"(a1), "r"(a2), "r"(a3), "r"(b0), "r"(b1));
}

// ---------------------------- CSR construction -----------------------------
// hist also records each edge's rank within its destination bucket
__global__ void hist_kernel(const int* __restrict__ dst) {
    const int stride = gridDim.x * blockDim.x;
    int i = blockIdx.x * blockDim.x + threadIdx.x;
#pragma unroll
    for (int j = 0; j < 8; j++, i += stride) {
        if (i < N_EDGES) g_rank[i] = atomicAdd(&g_deg[dst[i]], 1);
    }
}

__global__ void scan_fused_kernel() {
    extern __shared__ int sdeg[];
    __shared__ int warpsum[32];
    int t = threadIdx.x;
    for (int i = t; i < SCAN_PAD; i += SCAN_T)
        sdeg[i] = (i < N_NODES) ? g_deg[i] : 0;
    __syncthreads();

    int base = t * CHUNK;
    int sum = 0;
    for (int j = 0; j < CHUNK; j++) sum += sdeg[base + j];

    int lane = t & 31, wid = t >> 5;
    int incl = sum;
#pragma unroll
    for (int o = 1; o < 32; o <<= 1) {
        int u = __shfl_up_sync(0xffffffffu, incl, o);
        if (lane >= o) incl += u;
    }
    if (lane == 31) warpsum[wid] = incl;
    __syncthreads();
    if (wid == 0) {
        int v = warpsum[lane];
        int wi = v;
#pragma unroll
        for (int o = 1; o < 32; o <<= 1) {
            int u = __shfl_up_sync(0xffffffffu, wi, o);
            if (lane >= o) wi += u;
        }
        warpsum[lane] = wi - v;
        if (lane == 31) g_rowptr[N_NODES] = wi;
    }
    __syncthreads();

    int run = warpsum[wid] + (incl - sum);
    for (int j = 0; j < CHUNK; j++) {
        int d = sdeg[base + j];
        sdeg[base + j] = run;
        run += d;
    }
    __syncthreads();
    for (int i = t; i < N_NODES; i += SCAN_T)
        g_rowptr[i] = sdeg[i];
}

// no atomics: pos = rowptr[dst] + rank
__global__ void scatter_kernel(const int* __restrict__ src,
                               const int* __restrict__ dst,
                               const float* __restrict__ w) {
    const int stride = gridDim.x * blockDim.x;
    int i = blockIdx.x * blockDim.x + threadIdx.x;
#pragma unroll
    for (int j = 0; j < 8; j++, i += stride) {
        if (i < N_EDGES) {
            int pos = g_rowptr[dst[i]] + g_rank[i];
            g_edge[pos] = make_int2(src[i], __float_as_int(w[i]));
        }
    }
}

// ------------------- HMMA GEMM: 64 rows x 64 cols per block -----------------
// fp32-input variant (layer 1: A = x)
__global__ void gemm64_hmma_f32(const float* __restrict__ A,
                                const float* __restrict__ W,
                                __half* __restrict__ outh) {
    __shared__ __align__(16) __half As[64 * 72];
    __shared__ __align__(16) __half Ws[64 * 72];
    const int tid  = threadIdx.x;
    const int lane = tid & 31;
    const int w    = tid >> 5;
    const int row0 = blockIdx.x * 64;

    const float4* W4 = reinterpret_cast<const float4*>(W);
    for (int i = tid; i < 1024; i += 128) {
        float4 v = W4[i];
        int k = i >> 4, n = (i & 15) * 4;
        __half2* p = reinterpret_cast<__half2*>(&Ws[k * 72 + n]);
        p[0] = __floats2half2_rn(v.x, v.y);
        p[1] = __floats2half2_rn(v.z, v.w);
    }
    const float4* A4 = reinterpret_cast<const float4*>(A);
    for (int i = tid; i < 1024; i += 128) {
        int r = i >> 4, k = (i & 15) * 4;
        int grow = row0 + r;
        float4 v = (grow < N_NODES) ? A4[grow * 16 + (k >> 2)]
                                    : make_float4(0.f, 0.f, 0.f, 0.f);
        __half2* p = reinterpret_cast<__half2*>(&As[r * 72 + k]);
        p[0] = __floats2half2_rn(v.x, v.y);
        p[1] = __floats2half2_rn(v.z, v.w);
    }
    __syncthreads();

    float d[4][2][4];
#pragma unroll
    for (int m = 0; m < 4; m++)
#pragma unroll
        for (int j = 0; j < 2; j++)
#pragma unroll
            for (int c = 0; c < 4; c++) d[m][j][c] = 0.f;

    const int lrow = lane & 15;
    const int lcol = (lane >> 4) * 8;

#pragma unroll
    for (int ks = 0; ks < 4; ks++) {
        const int kk = ks * 16;
        unsigned b0, b1, b2, b3;
        ldsm_x4_t(b0, b1, b2, b3,
                  smem_u32(&Ws[(kk + lrow) * 72 + w * 16 + lcol]));
#pragma unroll
        for (int m = 0; m < 4; m++) {
            unsigned a0, a1, a2, a3;
            ldsm_x4(a0, a1, a2, a3,
                    smem_u32(&As[(m * 16 + lrow) * 72 + kk + lcol]));
            mma16816(d[m][0], a0, a1, a2, a3, b0, b1);
            mma16816(d[m][1], a0, a1, a2, a3, b2, b3);
        }
    }

    __half2* out2 = reinterpret_cast<__half2*>(outh);
    const int r_in = lane >> 2;
    const int cpair = (lane & 3);
#pragma unroll
    for (int m = 0; m < 4; m++) {
#pragma unroll
        for (int j = 0; j < 2; j++) {
            int col2 = (w * 16 + j * 8) / 2 + cpair;
            int g0 = row0 + m * 16 + r_in;
            int g1 = g0 + 8;
            if (g0 < N_NODES)
                out2[g0 * 32 + col2] = __floats2half2_rn(d[m][j][0], d[m][j][1]);
            if (g1 < N_NODES)
                out2[g1 * 32 + col2] = __floats2half2_rn(d[m][j][2], d[m][j][3]);
        }
    }
}

// half-input variant (layer 2: A = agg1 half output)
__global__ void gemm64_hmma_f16(const __half* __restrict__ A,
                                const float* __restrict__ W,
                                __half* __restrict__ outh) {
    __shared__ __align__(16) __half As[64 * 72];
    __shared__ __align__(16) __half Ws[64 * 72];
    const int tid  = threadIdx.x;
    const int lane = tid & 31;
    const int w    = tid >> 5;
    const int row0 = blockIdx.x * 64;

    const float4* W4 = reinterpret_cast<const float4*>(W);
    for (int i = tid; i < 1024; i += 128) {
        float4 v = W4[i];
        int k = i >> 4, n = (i & 15) * 4;
        __half2* p = reinterpret_cast<__half2*>(&Ws[k * 72 + n]);
        p[0] = __floats2half2_rn(v.x, v.y);
        p[1] = __floats2half2_rn(v.z, v.w);
    }
    const uint2* A2 = reinterpret_cast<const uint2*>(A);
    for (int i = tid; i < 1024; i += 128) {
        int r = i >> 4, k4 = (i & 15);
        int grow = row0 + r;
        uint2 v = (grow < N_NODES) ? A2[grow * 16 + k4] : make_uint2(0u, 0u);
        *reinterpret_cast<uint2*>(&As[r * 72 + k4 * 4]) = v;
    }
    __syncthreads();

    float d[4][2][4];
#pragma unroll
    for (int m = 0; m < 4; m++)
#pragma unroll
        for (int j = 0; j < 2; j++)
#pragma unroll
            for (int c = 0; c < 4; c++) d[m][j][c] = 0.f;

    const int lrow = lane & 15;
    const int lcol = (lane >> 4) * 8;

#pragma unroll
    for (int ks = 0; ks < 4; ks++) {
        const int kk = ks * 16;
        unsigned b0, b1, b2, b3;
        ldsm_x4_t(b0, b1, b2, b3,
                  smem_u32(&Ws[(kk + lrow) * 72 + w * 16 + lcol]));
#pragma unroll
        for (int m = 0; m < 4; m++) {
            unsigned a0, a1, a2, a3;
            ldsm_x4(a0, a1, a2, a3,
                    smem_u32(&As[(m * 16 + lrow) * 72 + kk + lcol]));
            mma16816(d[m][0], a0, a1, a2, a3, b0, b1);
            mma16816(d[m][1], a0, a1, a2, a3, b2, b3);
        }
    }

    __half2* out2 = reinterpret_cast<__half2*>(outh);
    const int r_in = lane >> 2;
    const int cpair = (lane & 3);
#pragma unroll
    for (int m = 0; m < 4; m++) {
#pragma unroll
        for (int j = 0; j < 2; j++) {
            int col2 = (w * 16 + j * 8) / 2 + cpair;
            int g0 = row0 + m * 16 + r_in;
            int g1 = g0 + 8;
            if (g0 < N_NODES)
                out2[g0 * 32 + col2] = __floats2half2_rn(d[m][j][0], d[m][j][1]);
            if (g1 < N_NODES)
                out2[g1 * 32 + col2] = __floats2half2_rn(d[m][j][2], d[m][j][3]);
        }
    }
}

// -------------------- CSR aggregation + bias + swish ------------------------
template<bool HALF_OUT>
__global__ void agg_swish_kernel(const __half2* __restrict__ hp,
                                 const float* __restrict__ bias,
                                 void* __restrict__ outv) {
    int warp = (blockIdx.x * blockDim.x + threadIdx.x) >> 5;
    int lane = threadIdx.x & 31;
    if (warp >= N_NODES) return;
    int beg = g_rowptr[warp];
    int end = g_rowptr[warp + 1];
    float2 acc = make_float2(0.f, 0.f);
    int e = beg;
    for (; e + 8 <= end; e += 8) {
        int2 ed[8];
#pragma unroll
        for (int j = 0; j < 8; j++) ed[j] = g_edge[e + j];
        float2 v[8];
#pragma unroll
        for (int j = 0; j < 8; j++) v[j] = __half22float2(hp[ed[j].x * 32 + lane]);
#pragma unroll
        for (int j = 0; j < 8; j++) {
            float w = __int_as_float(ed[j].y);
            acc.x = fmaf(w, v[j].x, acc.x);
            acc.y = fmaf(w, v[j].y, acc.y);
        }
    }
    for (; e + 2 <= end; e += 2) {
        int2 e0 = g_edge[e], e1 = g_edge[e + 1];
        float2 v0 = __half22float2(hp[e0.x * 32 + lane]);
        float2 v1 = __half22float2(hp[e1.x * 32 + lane]);
        float w0 = __int_as_float(e0.y), w1 = __int_as_float(e1.y);
        acc.x = fmaf(w0, v0.x, acc.x); acc.y = fmaf(w0, v0.y, acc.y);
        acc.x = fmaf(w1, v1.x, acc.x); acc.y = fmaf(w1, v1.y, acc.y);
    }
    if (e < end) {
        int2 e0 = g_edge[e];
        float2 v0 = __half22float2(hp[e0.x * 32 + lane]);
        float w0 = __int_as_float(e0.y);
        acc.x = fmaf(w0, v0.x, acc.x); acc.y = fmaf(w0, v0.y, acc.y);
    }
    float2 b = reinterpret_cast<const float2*>(bias)[lane];
    float ax = acc.x + b.x;
    float ay = acc.y + b.y;
    ax = ax / (1.f + __expf(-ax));
    ay = ay / (1.f + __expf(-ay));
    if (HALF_OUT) {
        reinterpret_cast<__half2*>(outv)[warp * 32 + lane] = __floats2half2_rn(ax, ay);
    } else {
        reinterpret_cast<float2*>(outv)[warp * 32 + lane] = make_float2(ax, ay);
    }
}

// -------- HMMA fused head: dense(100, swish) + dense(1, sigmoid) ------------
__global__ void head_hmma_kernel(const float* __restrict__ A,
                                 const float* __restrict__ Wd,
                                 const float* __restrict__ bd,
                                 const float* __restrict__ Wo,
                                 const float* __restrict__ bo,
                                 float* __restrict__ out) {
    __shared__ __align__(16) __half As[64 * 72];
    __shared__ __align__(16) __half Ws[64 * 120];   // [k][n], n padded to 112
    __shared__ float bdS[112];
    __shared__ float woS[112];
    const int tid  = threadIdx.x;
    const int lane = tid & 31;
    const int w    = tid >> 5;
    const int row0 = blockIdx.x * 64;

    for (int i = tid; i < 64 * 112; i += 128) {
        int k = i / 112, n = i % 112;
        float v = (n < 100) ? Wd[k * 100 + n] : 0.f;
        Ws[k * 120 + n] = __float2half_rn(v);
    }
    const float4* A4 = reinterpret_cast<const float4*>(A);
    for (int i = tid; i < 1024; i += 128) {
        int r = i >> 4, k = (i & 15) * 4;
        int grow = row0 + r;
        float4 v = (grow < N_NODES) ? A4[grow * 16 + (k >> 2)]
                                    : make_float4(0.f, 0.f, 0.f, 0.f);
        __half2* p = reinterpret_cast<__half2*>(&As[r * 72 + k]);
        p[0] = __floats2half2_rn(v.x, v.y);
        p[1] = __floats2half2_rn(v.z, v.w);
    }
    if (tid < 112) {
        bdS[tid] = (tid < 100) ? bd[tid] : 0.f;
        woS[tid] = (tid < 100) ? Wo[tid] : 0.f;
    }
    __syncthreads();

    float acc[14][4];
#pragma unroll
    for (int t = 0; t < 14; t++)
#pragma unroll
        for (int c = 0; c < 4; c++) acc[t][c] = 0.f;

    const int lrow = lane & 15;
    const int lcol = (lane >> 4) * 8;

#pragma unroll
    for (int ks = 0; ks < 4; ks++) {
        const int kk = ks * 16;
        unsigned a0, a1, a2, a3;
        ldsm_x4(a0, a1, a2, a3,
                smem_u32(&As[(w * 16 + lrow) * 72 + kk + lcol]));
#pragma unroll
        for (int t2 = 0; t2 < 7; t2++) {
            unsigned b0, b1, b2, b3;
            ldsm_x4_t(b0, b1, b2, b3,
                      smem_u32(&Ws[(kk + lrow) * 120 + t2 * 16 + lcol]));
            mma16816(acc[t2 * 2],     a0, a1, a2, a3, b0, b1);
            mma16816(acc[t2 * 2 + 1], a0, a1, a2, a3, b2, b3);
        }
    }

    const int r_in = lane >> 2;
    const int c2   = (lane & 3) * 2;
    float s0 = 0.f, s1 = 0.f;
#pragma unroll
    for (int t = 0; t < 14; t++) {
        int c = t * 8 + c2;
        float bb0 = bdS[c], bb1 = bdS[c + 1];
        float ww0 = woS[c], ww1 = woS[c + 1];
        float v;
        v = acc[t][0] + bb0; v = v / (1.f + __expf(-v)); s0 = fmaf(v, ww0, s0);
        v = acc[t][1] + bb1; v = v / (1.f + __expf(-v)); s0 = fmaf(v, ww1, s0);
        v = acc[t][2] + bb0; v = v / (1.f + __expf(-v)); s1 = fmaf(v, ww0, s1);
        v = acc[t][3] + bb1; v = v / (1.f + __expf(-v)); s1 = fmaf(v, ww1, s1);
    }
    s0 += __shfl_xor_sync(0xffffffffu, s0, 1);
    s0 += __shfl_xor_sync(0xffffffffu, s0, 2);
    s1 += __shfl_xor_sync(0xffffffffu, s1, 1);
    s1 += __shfl_xor_sync(0xffffffffu, s1, 2);
    if ((lane & 3) == 0) {
        float bias0 = bo[0];
        int g0 = row0 + w * 16 + r_in;
        int g1 = g0 + 8;
        if (g0 < N_NODES) out[g0] = 1.f / (1.f + __expf(-(s0 + bias0)));
        if (g1 < N_NODES) out[g1] = 1.f / (1.f + __expf(-(s1 + bias0)));
    }
}

// -------------------------------- launcher ----------------------------------
extern "C" void kernel_launch(void* const* d_in, const int* in_sizes, int n_in,
                              void* d_out, int out_size) {
    const float* x    = (const float*)d_in[0];
    const int*   esrc = (const int*)  d_in[1];
    const int*   edst = (const int*)  d_in[2];
    const float* ew   = (const float*)d_in[3];
    const float* W1   = (const float*)d_in[4];
    const float* b1   = (const float*)d_in[5];
    const float* W2   = (const float*)d_in[6];
    const float* b2   = (const float*)d_in[7];
    const float* Wd   = (const float*)d_in[8];
    const float* bd   = (const float*)d_in[9];
    const float* Wo   = (const float*)d_in[10];
    const float* bo   = (const float*)d_in[11];
    float* out = (float*)d_out;

    __half* h1h;  __half* h2h;  float* h2f;  int* degp;
    cudaGetSymbolAddress((void**)&h1h,  g_h1h);
    cudaGetSymbolAddress((void**)&h2h,  g_h2h);
    cudaGetSymbolAddress((void**)&h2f,  g_h2f);
    cudaGetSymbolAddress((void**)&degp, g_deg);

    static cudaStream_t s2 = nullptr;
    static cudaEvent_t evFork = nullptr, evJoin = nullptr;
    if (!s2) {
        cudaStreamCreateWithFlags(&s2, cudaStreamNonBlocking);
        cudaEventCreateWithFlags(&evFork, cudaEventDisableTiming);
        cudaEventCreateWithFlags(&evJoin, cudaEventDisableTiming);
        cudaFuncSetAttribute(scan_fused_kernel,
                             cudaFuncAttributeMaxDynamicSharedMemorySize,
                             SCAN_PAD * (int)sizeof(int));
    }

    const int aggBlocks   = (N_NODES * 32 + 255) / 256;
    const int gemmBlocks  = (N_NODES + 63) / 64;
    const int edge8Blocks = (N_EDGES / 8 + 255) / 256;

    // --- fork: gemm1 runs concurrent with the CSR build ---
    cudaEventRecord(evFork, 0);
    cudaStreamWaitEvent(s2, evFork, 0);
    gemm64_hmma_f32<<<gemmBlocks, 128, 0, s2>>>(x, W1, h1h);
    cudaEventRecord(evJoin, s2);

    // --- CSR build (main stream) ---
    cudaMemsetAsync(degp, 0, N_NODES * sizeof(int));
    hist_kernel<<<edge8Blocks, 256>>>(edst);
    scan_fused_kernel<<<1, SCAN_T, SCAN_PAD * sizeof(int)>>>();
    scatter_kernel<<<edge8Blocks, 256>>>(esrc, edst, ew);

    // --- join, then layer 1 aggregation ---
    cudaStreamWaitEvent(0, evJoin, 0);
    agg_swish_kernel<true><<<aggBlocks, 256>>>((const __half2*)h1h, b1, h2h);

    // --- layer 2 ---
    gemm64_hmma_f16<<<gemmBlocks, 128>>>(h2h, W2, h1h);
    agg_swish_kernel<false><<<aggBlocks, 256>>>((const __half2*)h1h, b2, h2f);

    // --- HMMA fused head ---
    head_hmma_kernel<<<gemmBlocks, 128>>>(h2f, Wd, bd, Wo, bo, out);
}